// round 7
// baseline (speedup 1.0000x reference)
#include <cuda_runtime.h>
#include <cmath>

// net_LSTM_21534966022336: T=4096, B=8192, I=H=1 -> 8192 independent scalar
// LSTM chains; latency-bound. Calibrated: period = 2L + K, L ~= 39 cyc
// (effective MUFU.TANH RAW). R5 had K=26 (terminal fma bound to the 3rd
// MUFU, +21 issue offset). This round: i-gate tanh via FFMA polynomial,
// but with program order that issues the f/g MUFUs FIRST so the ~13 poly
// instructions land in the MUFU-wait shadow instead of delaying them
// (R6's mistake). Terminal fma binds the 2nd MUFU (+13): K -> 18.

#ifndef LSTM_T
#define LSTM_T 4096
#endif
#ifndef LSTM_B
#define LSTM_B 8192
#endif

__device__ __forceinline__ float tanh_approx(float v) {
    float y;
    asm("tanh.approx.f32 %0, %1;" : "=f"(y) : "f"(v));
    return y;
}

// One-time per-thread fit: tanh(a) ~= a * q(a^2) on [-3,3], q = sum d_m y^m,
// deg 7 in y (odd deg-15 in a). Interpolation at 8 Chebyshev-spaced nodes;
// 8x8 Vandermonde solved by fp64 Gaussian elimination against device tanh().
__device__ void fit_tanh_poly(float* df) {
    const double R = 3.0;
    const double nodes[8] = {0.098017, 0.290285, 0.471397, 0.634393,
                             0.773010, 0.881921, 0.956940, 0.995185};
    double A[8][9];
#pragma unroll
    for (int j = 0; j < 8; ++j) {
        const double a = R * nodes[j];
        const double y = a * a;
        double p = 1.0;
#pragma unroll
        for (int m = 0; m < 8; ++m) { A[j][m] = p; p *= y; }
        A[j][8] = tanh(a) / a;
    }
#pragma unroll
    for (int k = 0; k < 8; ++k) {
        const double inv = 1.0 / A[k][k];
#pragma unroll
        for (int i = 0; i < 8; ++i) {
            if (i > k) {
                const double f = A[i][k] * inv;
#pragma unroll
                for (int m = 0; m < 9; ++m) A[i][m] -= f * A[k][m];
            }
        }
    }
    double d[8];
#pragma unroll
    for (int k = 7; k >= 0; --k) {
        double s = A[k][8];
#pragma unroll
        for (int m = 0; m < 8; ++m)
            if (m > k) s -= A[k][m] * d[m];
        d[k] = s / A[k][k];
    }
#pragma unroll
    for (int m = 0; m < 8; ++m) df[m] = (float)d[m];
}

__global__ void __launch_bounds__(128, 1)
lstm_scalar_chain_kernel(const float* __restrict__ x,
                         const float* __restrict__ h0,
                         const float* __restrict__ c0,
                         const float* __restrict__ w_ih,
                         const float* __restrict__ w_hh,
                         float* __restrict__ out,
                         int out_size) {
    const int b = blockIdx.x * blockDim.x + threadIdx.x;
    if (b >= LSTM_B) return;

    float d[8];
    fit_tanh_poly(d);
    const float d0 = d[0], d1 = d[1], d2 = d[2], d3 = d[3];
    const float d4 = d[4], d5 = d[5], d6 = d[6], d7 = d[7];

    // Pre-scaled shared scalar weights (gate order i, f, g, o).
    const float wi_i = 0.50f * w_ih[0];
    const float wi_f = 0.50f * w_ih[1];
    const float wi_g =         w_ih[2];
    const float wi_o = 0.50f * w_ih[3];
    const float wh_i = 0.25f * w_hh[0];
    const float wh_f = 0.25f * w_hh[1];
    const float wh_g = 0.50f * w_hh[2];
    const float wh_o = 0.25f * w_hh[3];

    // Seed: tc*(1+to) = 2*h0 -> tc = 2*h0, to = 0 (exact).
    float tc = 2.0f * h0[b];
    float to = 0.0f;
    float c  = c0[b];

    const float* xp = x + b;
    float*       op = out + b;

    // 4-phase ring of 8-wide x buffers: reloaded in place after consumption.
    float xr[32];
#pragma unroll
    for (int u = 0; u < 32; ++u) xr[u] = xp[u * LSTM_B];

    for (int t0 = 0; t0 < LSTM_T; t0 += 32) {
#pragma unroll
        for (int ph = 0; ph < 4; ++ph) {
#pragma unroll
            for (int u = 0; u < 8; ++u) {
                const int t = t0 + ph * 8 + u;
                const float xv = xr[ph * 8 + u];

                // ---- Critical MUFUs first: f then g, issued ASAP after tc.
                const float xf = xv * wi_f;
                const float xg = xv * wi_g;
                const float sf = fmaf(to, wh_f, wh_f);
                const float sg = fmaf(to, wh_g, wh_g);
                const float af = fmaf(tc, sf, xf);
                const float ag = fmaf(tc, sg, xg);
                const float tf = tanh_approx(af);   // MUFU slot +5
                const float tg = tanh_approx(ag);   // MUFU slot +13 (terminal)

                // ---- i-gate polynomial: lives in the 39-cycle MUFU shadow.
                const float xi  = xv * wi_i;
                const float si_ = fmaf(to, wh_i, wh_i);
                const float ai  = fmaf(tc, si_, xi);
                const float yy  = ai * ai;
                const float yc  = fminf(yy, 9.0f);
                const float acl = fmaxf(fminf(ai, 3.0f), -3.0f);
                const float e0  = fmaf(d1, yc, d0);
                const float e1  = fmaf(d3, yc, d2);
                const float e2  = fmaf(d5, yc, d4);
                const float e3  = fmaf(d7, yc, d6);
                const float y2  = yc * yc;
                const float g0  = fmaf(e1, y2, e0);
                const float g1  = fmaf(e3, y2, e2);
                const float y4  = y2 * y2;
                const float qq  = fmaf(g1, y4, g0);
                const float ti  = acl * qq;            // tanh(a_i)
                const float k   = fmaf(ti, 0.5f, 0.5f); // sigmoid(i), ready ~+45

                // ---- o-gate MUFU: fully off-path (consumed next step).
                const float xo = xv * wi_o;
                const float so = fmaf(to, wh_o, wh_o);
                const float ao = fmaf(tc, so, xo);
                const float to2 = tanh_approx(ao);

                const float hc = 0.5f * c;

                // c' = sigmoid(f)*c + sigmoid(i)*tanh(g); terminal on tg (2nd MUFU).
                const float v = fmaf(tf, hc, hc);
                c = fmaf(tg, k, v);

                const float tc2 = tanh_approx(c);

                // h = sigmoid(o)*tanh(c); off the critical path.
                const float sho = fmaf(to2, 0.5f, 0.5f);
                op[t * LSTM_B] = tc2 * sho;

                tc = tc2;
                to = to2;
            }
            // Reload this phase's buffer for t0+32 (clamped dummy at tail).
#pragma unroll
            for (int u = 0; u < 8; ++u) {
                int t = t0 + 32 + ph * 8 + u;
                t = (t < LSTM_T) ? t : (LSTM_T - 1);
                xr[ph * 8 + u] = xp[t * LSTM_B];
            }
        }
    }

    // h_n, c_n appended after out (tuple flattening order).
    if (out_size >= LSTM_T * LSTM_B + 2 * LSTM_B) {
        out[LSTM_T * LSTM_B + b]          = tc * fmaf(to, 0.5f, 0.5f);
        out[LSTM_T * LSTM_B + LSTM_B + b] = c;
    }
}

extern "C" void kernel_launch(void* const* d_in, const int* in_sizes, int n_in,
                              void* d_out, int out_size) {
    const float* x    = (const float*)d_in[0];
    const float* h0   = (const float*)d_in[1];
    const float* c0   = (const float*)d_in[2];
    const float* w_ih = (const float*)d_in[3];
    const float* w_hh = (const float*)d_in[4];
    float* out = (float*)d_out;

    const int threads = 128;
    const int blocks  = (LSTM_B + threads - 1) / threads;
    lstm_scalar_chain_kernel<<<blocks, threads>>>(x, h0, c0, w_ih, w_hh, out, out_size);
}

// round 8
// speedup vs baseline: 1.1378x; 1.1378x over previous
#include <cuda_runtime.h>

// net_LSTM_21534966022336: T=4096, B=8192, I=H=1 -> 8192 independent scalar
// LSTM chains; latency-bound: wall = 4096 * period.
// Calibrated: period = 2L + K, L ~= 39 (effective MUFU.TANH RAW),
// K floor = 26 with 3 gate MUFUs (rt_SMSP=8 puts the 3rd at +21).
// R6/R7 poly experiments regressed (poly chain also hangs off tc, depth ~= L).
// This round = R5 structure + store software-pipelined by one step so the
// STG (and its tc2-wait) never sits ahead of the next step's critical
// FFMAs/MUFUs in issue order, + cheaper per-phase prefetch clamp.

#ifndef LSTM_T
#define LSTM_T 4096
#endif
#ifndef LSTM_B
#define LSTM_B 8192
#endif

__device__ __forceinline__ float tanh_approx(float v) {
    float y;
    asm("tanh.approx.f32 %0, %1;" : "=f"(y) : "f"(v));
    return y;
}

__global__ void __launch_bounds__(128, 1)
lstm_scalar_chain_kernel(const float* __restrict__ x,
                         const float* __restrict__ h0,
                         const float* __restrict__ c0,
                         const float* __restrict__ w_ih,
                         const float* __restrict__ w_hh,
                         float* __restrict__ out,
                         int out_size) {
    const int b = blockIdx.x * blockDim.x + threadIdx.x;
    if (b >= LSTM_B) return;

    // Pre-scaled shared scalar weights (gate order i, f, g, o).
    const float wi_i = 0.50f * w_ih[0];
    const float wi_f = 0.50f * w_ih[1];
    const float wi_g =         w_ih[2];
    const float wi_o = 0.50f * w_ih[3];
    const float wh_i = 0.25f * w_hh[0];
    const float wh_f = 0.25f * w_hh[1];
    const float wh_g = 0.50f * w_hh[2];
    const float wh_o = 0.25f * w_hh[3];

    // Seed: tc*(1+to) = 2*h0 -> tc = 2*h0, to = 0 (exact).
    float tc = 2.0f * h0[b];
    float to = 0.0f;
    float c  = c0[b];

    // Pending output store (h of the previous step), pipelined by one step.
    // Deterministic dummy for the very first store (overwritten by real h0).
    float h_pend = 0.0f;

    const float* xp = x + b;
    float*       op = out + b;

    // 4-phase ring of 8-wide x buffers: reloaded in place after consumption
    // (prefetch distance = 24 steps, no register rotation).
    float xr[32];
#pragma unroll
    for (int u = 0; u < 32; ++u) xr[u] = xp[u * LSTM_B];

    for (int t0 = 0; t0 < LSTM_T; t0 += 32) {
#pragma unroll
        for (int ph = 0; ph < 4; ++ph) {
#pragma unroll
            for (int u = 0; u < 8; ++u) {
                const float xv = xr[ph * 8 + u];

                // Off-path operands, ready before tc lands:
                const float xf = xv * wi_f;
                const float xg = xv * wi_g;
                const float xi = xv * wi_i;
                const float xo = xv * wi_o;
                const float sf = fmaf(to, wh_f, wh_f);
                const float sg = fmaf(to, wh_g, wh_g);
                const float si = fmaf(to, wh_i, wh_i);
                const float so = fmaf(to, wh_o, wh_o);
                const float hc = 0.5f * c;

                // Critical: one FFMA after tc, straight into MUFU (f,g,i).
                const float af = fmaf(tc, sf, xf);
                const float ag = fmaf(tc, sg, xg);
                const float ai = fmaf(tc, si, xi);
                const float tf = tanh_approx(af);   // +5
                const float tg = tanh_approx(ag);   // +13
                const float ti = tanh_approx(ai);   // +21 (terminal)

                // o-gate MUFU: off-path (consumed next step).
                const float ao  = fmaf(tc, so, xo);
                const float to2 = tanh_approx(ao);

                // Previous step's output store: data long ready, issued in
                // the gate-MUFU wait shadow. (ph==0,u==0) clamps for t0==0.
                if (ph == 0 && u == 0) {
                    int tp = t0 - 1;
                    tp = (tp > 0) ? tp : 0;
                    op[tp * LSTM_B] = h_pend;
                } else {
                    op[(t0 + ph * 8 + u - 1) * LSTM_B] = h_pend;
                }

                // c' = sigmoid(f)*c + sigmoid(i)*tanh(g); terminal fma on ti.
                const float v   = fmaf(tf, hc, hc);   // 2*sig(f)*c / 2... (c*sig(f))
                const float htg = 0.5f * tg;
                const float s   = v + htg;
                c = fmaf(ti, htg, s);

                const float tc2 = tanh_approx(c);

                // h = sigmoid(o)*tanh(c); computed now, stored next step.
                const float sho = fmaf(to2, 0.5f, 0.5f);
                h_pend = tc2 * sho;

                tc = tc2;
                to = to2;
            }
            // Reload this phase's buffer for t0+32; single clamped base
            // index per phase (tail loads valid-but-unused).
            {
                int tb = t0 + 32 + ph * 8;
                tb = (tb <= LSTM_T - 8) ? tb : (LSTM_T - 8);
                const float* xq = xp + tb * LSTM_B;
#pragma unroll
                for (int u = 0; u < 8; ++u)
                    xr[ph * 8 + u] = xq[u * LSTM_B];
            }
        }
    }

    // Final pending output (t = T-1), then h_n, c_n (tuple flattening order).
    op[(LSTM_T - 1) * LSTM_B] = h_pend;
    if (out_size >= LSTM_T * LSTM_B + 2 * LSTM_B) {
        out[LSTM_T * LSTM_B + b]          = h_pend;   // h_n = last h
        out[LSTM_T * LSTM_B + LSTM_B + b] = c;        // c_n
    }
}

extern "C" void kernel_launch(void* const* d_in, const int* in_sizes, int n_in,
                              void* d_out, int out_size) {
    const float* x    = (const float*)d_in[0];
    const float* h0   = (const float*)d_in[1];
    const float* c0   = (const float*)d_in[2];
    const float* w_ih = (const float*)d_in[3];
    const float* w_hh = (const float*)d_in[4];
    float* out = (float*)d_out;

    const int threads = 128;
    const int blocks  = (LSTM_B + threads - 1) / threads;
    lstm_scalar_chain_kernel<<<blocks, threads>>>(x, h0, c0, w_ih, w_hh, out, out_size);
}